// round 1
// baseline (speedup 1.0000x reference)
#include <cuda_runtime.h>
#include <math.h>

// Problem constants
#define TT   128
#define BB   8
#define II   240
#define HH   1024
#define G4   4096
#define EE   512
#define U1   65        // U+1
#define VV   1024
#define NBLK 128       // persistent grid size (<= 148 SMs -> co-resident)
#define WSTR 1028      // padded SMEM row stride (floats), 16B-aligned, bank-spread

// ---------------- scratch (no allocations allowed) ----------------
__device__ float g_xp_enc[TT * BB * G4];   // 16.8 MB
__device__ float g_xp_dec[U1 * BB * G4];   //  8.5 MB
__device__ float g_decin [U1 * BB * EE];
__device__ float g_f     [TT * BB * HH];
__device__ float g_gg    [U1 * BB * HH];
__device__ float g_lf    [TT * BB * VV];
__device__ float g_lg    [U1 * BB * VV];
__device__ float g_h     [2][BB * HH];     // double-buffered hidden, layout [b][k]
__device__ unsigned g_barcnt;              // zero-initialized
__device__ unsigned g_bargen;              // monotonically increasing across replays

// ---------------- software grid barrier ----------------
// Protocol: counter returns to 0 after every barrier; generation flag is
// monotonic across kernel launches and graph replays (deterministic).
__device__ __forceinline__ void grid_bar(unsigned target, unsigned nb) {
    __syncthreads();
    if (threadIdx.x == 0) {
        __threadfence();
        if (atomicAdd(&g_barcnt, 1u) == nb - 1u) {
            g_barcnt = 0u;
            __threadfence();
            atomicExch(&g_bargen, target);
        } else {
            volatile unsigned* vg = &g_bargen;
            while ((int)(*vg - target) < 0) { }
            __threadfence();
        }
    }
    __syncthreads();
}

// ---------------- generic C = A * B^T (+bias) tiled GEMM ----------------
// A: [M][K] row-major lda, B: [N][K] row-major ldb, C: [M][N] ldc, bias over N (or null)
// BM=BN=128, BK=8, 256 threads, 8x8 per-thread tile.
__global__ __launch_bounds__(256) void gemm_tn(
    const float* __restrict__ A, const float* __restrict__ B,
    const float* __restrict__ bias, float* __restrict__ C,
    int M, int N, int K, int lda, int ldb, int ldc)
{
    __shared__ float As[8][132];
    __shared__ float Bs[8][132];
    const int tid = threadIdx.x;
    const int bm = blockIdx.y * 128, bn = blockIdx.x * 128;
    const int tx = tid & 15, ty = tid >> 4;
    const int lr = tid >> 1;          // 0..127
    const int lk = (tid & 1) * 4;     // 0 or 4

    float acc[8][8];
#pragma unroll
    for (int i = 0; i < 8; i++)
#pragma unroll
        for (int j = 0; j < 8; j++) acc[i][j] = 0.f;

    for (int k0 = 0; k0 < K; k0 += 8) {
        float4 va = make_float4(0.f, 0.f, 0.f, 0.f);
        float4 vb = make_float4(0.f, 0.f, 0.f, 0.f);
        const int gm = bm + lr;
        if (gm < M) va = *(const float4*)(A + (size_t)gm * lda + k0 + lk);
        const int gn = bn + lr;
        if (gn < N) vb = *(const float4*)(B + (size_t)gn * ldb + k0 + lk);
        As[lk + 0][lr] = va.x; As[lk + 1][lr] = va.y;
        As[lk + 2][lr] = va.z; As[lk + 3][lr] = va.w;
        Bs[lk + 0][lr] = vb.x; Bs[lk + 1][lr] = vb.y;
        Bs[lk + 2][lr] = vb.z; Bs[lk + 3][lr] = vb.w;
        __syncthreads();
#pragma unroll
        for (int kk = 0; kk < 8; kk++) {
            float4 a0 = *(const float4*)&As[kk][ty * 8];
            float4 a1 = *(const float4*)&As[kk][ty * 8 + 4];
            float4 b0 = *(const float4*)&Bs[kk][tx * 8];
            float4 b1 = *(const float4*)&Bs[kk][tx * 8 + 4];
            const float a[8] = {a0.x, a0.y, a0.z, a0.w, a1.x, a1.y, a1.z, a1.w};
            const float b[8] = {b0.x, b0.y, b0.z, b0.w, b1.x, b1.y, b1.z, b1.w};
#pragma unroll
            for (int i = 0; i < 8; i++)
#pragma unroll
                for (int j = 0; j < 8; j++) acc[i][j] += a[i] * b[j];
        }
        __syncthreads();
    }

    float bv[8];
#pragma unroll
    for (int j = 0; j < 8; j++) bv[j] = bias ? bias[bn + tx * 8 + j] : 0.f;
#pragma unroll
    for (int i = 0; i < 8; i++) {
        const int gm = bm + ty * 8 + i;
        if (gm >= M) continue;
        float* cp = C + (size_t)gm * ldc + bn + tx * 8;
        float4 r0 = make_float4(acc[i][0] + bv[0], acc[i][1] + bv[1],
                                acc[i][2] + bv[2], acc[i][3] + bv[3]);
        float4 r1 = make_float4(acc[i][4] + bv[4], acc[i][5] + bv[5],
                                acc[i][6] + bv[6], acc[i][7] + bv[7]);
        *(float4*)(cp)     = r0;
        *(float4*)(cp + 4) = r1;
    }
}

// ---------------- decoder input: [sos; emb[y]] ----------------
__global__ void decin_k(const int* __restrict__ y, const float* __restrict__ emb,
                        float* __restrict__ dst)
{
    const int i = blockIdx.x * blockDim.x + threadIdx.x;  // over U1*BB*EE
    if (i >= U1 * BB * EE) return;
    const int e = i % EE;
    const int b = (i / EE) % BB;
    const int u = i / (EE * BB);
    float v = 0.f;
    if (u > 0) {
        const int tok = y[(u - 1) * BB + b];
        v = emb[(size_t)tok * EE + e];
    }
    dst[i] = v;
}

// ---------------- persistent LSTM recurrence ----------------
// 128 blocks x 256 threads. Block bid owns hidden units [bid*8, bid*8+8).
// Whh rows for the 4 gates of those 8 units live in SMEM for all steps.
// Per step: all blocks copy full h (8x1024) from global into SMEM, each
// thread computes one (gate-row, batch) dot product over K=1024, epilogue
// threads (64) apply the LSTM cell and publish the new h slice.
__global__ __launch_bounds__(256) void lstm_rec(
    const float* __restrict__ Whh, const float* __restrict__ xp,
    float* __restrict__ hout, int nsteps)
{
    extern __shared__ float sm[];
    float* Ws = sm;                    // 32 * WSTR
    float* Hs = Ws + 32 * WSTR;        // 8 * WSTR
    float* Gt = Hs + 8 * WSTR;         // 32*8 gates
    float* Cs = Gt + 256;              // 64 cell states

    const int tid = threadIdx.x;
    const int bid = blockIdx.x;
    const int hbase = bid * 8;

    // Load weight slice into SMEM: Ws[c][k], c = gate*8 + unit
    for (int c = 0; c < 32; c++) {
        const int q = c >> 3, r = c & 7;
        const float4* src = (const float4*)(Whh + ((size_t)q * HH + hbase + r) * HH);
        ((float4*)(Ws + c * WSTR))[tid] = src[tid];
    }
    if (tid < 64) {
        Cs[tid] = 0.f;
        const int r = tid >> 3, b = tid & 7;
        g_h[0][b * HH + hbase + r] = 0.f;
        __threadfence();
    }

    volatile unsigned* vgen = &g_bargen;
    const unsigned base = *vgen;
    grid_bar(base + 1, NBLK);
    unsigned bt = base + 2;

    const int cc = tid >> 3;           // gate-row column 0..31
    const int b  = tid & 7;
    const int q  = cc >> 3, r = cc & 7;
    const float4* wp = (const float4*)(Ws + cc * WSTR);
    const float4* hp = (const float4*)(Hs + b * WSTR);

    for (int t = 0; t < nsteps; t++) {
        const int rp  = t & 1;
        const int wpb = (t + 1) & 1;
        const float4* hbuf = (const float4*)g_h[rp];
#pragma unroll
        for (int i = 0; i < 8; i++) {
            const int idx = tid + i * 256;          // 0..2047 float4s
            const int bb_ = idx >> 8, k4 = idx & 255;
            ((float4*)(Hs + bb_ * WSTR))[k4] = hbuf[idx];
        }
        const float xg = xp[((size_t)t * BB + b) * G4 + q * HH + hbase + r];
        __syncthreads();

        float a0 = 0.f, a1 = 0.f, a2 = 0.f, a3 = 0.f;
#pragma unroll 8
        for (int k4 = 0; k4 < 256; k4++) {
            const float4 w = wp[k4];
            const float4 h = hp[k4];
            a0 += w.x * h.x; a1 += w.y * h.y;
            a2 += w.z * h.z; a3 += w.w * h.w;
        }
        Gt[cc * 8 + b] = (a0 + a1) + (a2 + a3) + xg;
        __syncthreads();

        if (tid < 64) {
            const int r2 = tid >> 3, b2 = tid & 7;
            const float gi = Gt[(0  + r2) * 8 + b2];
            const float gf = Gt[(8  + r2) * 8 + b2];
            const float gc = Gt[(16 + r2) * 8 + b2];
            const float go = Gt[(24 + r2) * 8 + b2];
            const float si = 1.f / (1.f + expf(-gi));
            const float sf = 1.f / (1.f + expf(-gf));
            const float so = 1.f / (1.f + expf(-go));
            const float tg = tanhf(gc);
            const float cn = sf * Cs[tid] + si * tg;
            Cs[tid] = cn;
            const float hv = so * tanhf(cn);
            g_h[wpb][b2 * HH + hbase + r2] = hv;
            hout[((size_t)t * BB + b2) * HH + hbase + r2] = hv;
            __threadfence();
        }
        grid_bar(bt, NBLK);
        bt++;
    }
}

// ---------------- final broadcast add: out[b][t][u][v] = lf + lg + bias ----------------
__global__ __launch_bounds__(256) void addk(
    const float* __restrict__ lf, const float* __restrict__ lg,
    const float* __restrict__ bias, float* __restrict__ out)
{
    const int u = blockIdx.x, t = blockIdx.y, b = blockIdx.z;
    const int v4 = threadIdx.x;  // 256 float4s = 1024 floats
    const float4 a = ((const float4*)(lf + ((size_t)(t * BB + b)) * VV))[v4];
    const float4 c = ((const float4*)(lg + ((size_t)(u * BB + b)) * VV))[v4];
    const float4 bb = ((const float4*)bias)[v4];
    float4 r;
    r.x = a.x + c.x + bb.x; r.y = a.y + c.y + bb.y;
    r.z = a.z + c.z + bb.z; r.w = a.w + c.w + bb.w;
    ((float4*)(out + (((size_t)b * TT + t) * U1 + u) * VV))[v4] = r;
}

// ---------------- launch ----------------
extern "C" void kernel_launch(void* const* d_in, const int* in_sizes, int n_in,
                              void* d_out, int out_size)
{
    const float* x        = (const float*)d_in[0];
    const int*   y        = (const int*)  d_in[2];
    const float* enc_Wih  = (const float*)d_in[4];
    const float* enc_Whh  = (const float*)d_in[5];
    const float* enc_b    = (const float*)d_in[6];
    const float* emb      = (const float*)d_in[7];
    const float* dec_Wih  = (const float*)d_in[8];
    const float* dec_Whh  = (const float*)d_in[9];
    const float* dec_b    = (const float*)d_in[10];
    const float* fc_W     = (const float*)d_in[11];
    const float* fc_b     = (const float*)d_in[12];
    float* out = (float*)d_out;

    float *xp_enc, *xp_dec, *decin, *f, *g, *lf, *lg;
    cudaGetSymbolAddress((void**)&xp_enc, g_xp_enc);
    cudaGetSymbolAddress((void**)&xp_dec, g_xp_dec);
    cudaGetSymbolAddress((void**)&decin,  g_decin);
    cudaGetSymbolAddress((void**)&f,      g_f);
    cudaGetSymbolAddress((void**)&g,      g_gg);
    cudaGetSymbolAddress((void**)&lf,     g_lf);
    cudaGetSymbolAddress((void**)&lg,     g_lg);

    const int smem = (32 * WSTR + 8 * WSTR + 256 + 64) * (int)sizeof(float);
    cudaFuncSetAttribute(lstm_rec, cudaFuncAttributeMaxDynamicSharedMemorySize, smem);

    // 1) Encoder input projection: [1024,4096] = x[1024,240] @ enc_Wih^T + b
    gemm_tn<<<dim3(G4 / 128, (TT * BB) / 128), 256>>>(
        x, enc_Wih, enc_b, xp_enc, TT * BB, G4, II, II, II, G4);

    // 2) Decoder input sequence + projection
    decin_k<<<(U1 * BB * EE + 255) / 256, 256>>>(y, emb, decin);
    gemm_tn<<<dim3(G4 / 128, (U1 * BB + 127) / 128), 256>>>(
        decin, dec_Wih, dec_b, xp_dec, U1 * BB, G4, EE, EE, EE, G4);

    // 3) Recurrences (persistent, grid-barrier)
    lstm_rec<<<NBLK, 256, smem>>>(enc_Whh, xp_enc, f, TT);
    lstm_rec<<<NBLK, 256, smem>>>(dec_Whh, xp_dec, g, U1);

    // 4) Joint projections: lf = f @ Wf^T, lg = g @ Wg^T  (fc_W is [V][2048])
    gemm_tn<<<dim3(VV / 128, (TT * BB) / 128), 256>>>(
        f, fc_W, (const float*)0, lf, TT * BB, VV, HH, HH, HH + HH, VV);
    gemm_tn<<<dim3(VV / 128, (U1 * BB + 127) / 128), 256>>>(
        g, fc_W + HH, (const float*)0, lg, U1 * BB, VV, HH, HH, HH + HH, VV);

    // 5) Broadcast add -> out [B][T][U+1][V]
    addk<<<dim3(U1, TT, BB), 256>>>(lf, lg, fc_b, out);
}

// round 2
// speedup vs baseline: 1.6364x; 1.6364x over previous
#include <cuda_runtime.h>
#include <math.h>

// Problem constants
#define TT   128
#define BB   8
#define II   240
#define HH   1024
#define G4   4096
#define EE   512
#define U1   65        // U+1
#define VV   1024
#define NBLK 128       // persistent grid size (<= 148 SMs -> co-resident)
#define WSTR 1028      // padded SMEM row stride (floats), 16B-aligned

// ---------------- scratch (no allocations allowed) ----------------
__device__ float g_xp_enc[TT * BB * G4];   // 16.8 MB
__device__ float g_xp_dec[U1 * BB * G4];   //  8.5 MB
__device__ float g_decin [U1 * BB * EE];
__device__ float g_f     [TT * BB * HH];
__device__ float g_gg    [U1 * BB * HH];
__device__ float g_lf    [TT * BB * VV];
__device__ float g_lg    [U1 * BB * VV];
__device__ float g_h     [2][BB * HH];     // double-buffered hidden, layout [b][k]
__device__ unsigned g_barcnt;              // zero-initialized
__device__ unsigned g_bargen;              // monotonic across replays

// ---------------- packed f32x2 helpers ----------------
__device__ __forceinline__ void ffma2(unsigned long long& d,
                                      unsigned long long a,
                                      unsigned long long b) {
    asm("fma.rn.f32x2 %0, %1, %2, %0;" : "+l"(d) : "l"(a), "l"(b));
}
__device__ __forceinline__ float hsum2(unsigned long long u) {
    float x, y;
    asm("mov.b64 {%0,%1}, %2;" : "=f"(x), "=f"(y) : "l"(u));
    return x + y;
}

// ---------------- software grid barrier ----------------
__device__ __forceinline__ void grid_bar(unsigned target, unsigned nb) {
    __syncthreads();
    if (threadIdx.x == 0) {
        __threadfence();
        if (atomicAdd(&g_barcnt, 1u) == nb - 1u) {
            g_barcnt = 0u;
            __threadfence();
            atomicExch(&g_bargen, target);
        } else {
            volatile unsigned* vg = &g_bargen;
            while ((int)(*vg - target) < 0) { }
            __threadfence();
        }
    }
    __syncthreads();
}

// ---------------- C = A * B^T (+bias), BM=128 BN=64 BK=8, 256 thr, 8x4 tile ----------------
__global__ __launch_bounds__(256) void gemm_tn(
    const float* __restrict__ A, const float* __restrict__ B,
    const float* __restrict__ bias, float* __restrict__ C,
    int M, int N, int K, int lda, int ldb, int ldc)
{
    __shared__ float As[8][132];
    __shared__ float Bs[8][68];
    const int tid = threadIdx.x;
    const int bm = blockIdx.y * 128, bn = blockIdx.x * 64;
    const int tx = tid & 15, ty = tid >> 4;   // tx: n (16x4), ty: m (16x8)
    const int lr = tid >> 1;                  // 0..127
    const int lk = (tid & 1) * 4;

    float acc[8][4];
#pragma unroll
    for (int i = 0; i < 8; i++)
#pragma unroll
        for (int j = 0; j < 4; j++) acc[i][j] = 0.f;

    for (int k0 = 0; k0 < K; k0 += 8) {
        float4 va = make_float4(0.f, 0.f, 0.f, 0.f);
        const int gm = bm + lr;
        if (gm < M) va = *(const float4*)(A + (size_t)gm * lda + k0 + lk);
        As[lk + 0][lr] = va.x; As[lk + 1][lr] = va.y;
        As[lk + 2][lr] = va.z; As[lk + 3][lr] = va.w;
        if (tid < 128) {
            const int gn = bn + lr;
            float4 vb = make_float4(0.f, 0.f, 0.f, 0.f);
            if (gn < N) vb = *(const float4*)(B + (size_t)gn * ldb + k0 + lk);
            Bs[lk + 0][lr] = vb.x; Bs[lk + 1][lr] = vb.y;
            Bs[lk + 2][lr] = vb.z; Bs[lk + 3][lr] = vb.w;
        }
        __syncthreads();
#pragma unroll
        for (int kk = 0; kk < 8; kk++) {
            float4 a0 = *(const float4*)&As[kk][ty * 8];
            float4 a1 = *(const float4*)&As[kk][ty * 8 + 4];
            float4 b0 = *(const float4*)&Bs[kk][tx * 4];
            const float a[8] = {a0.x, a0.y, a0.z, a0.w, a1.x, a1.y, a1.z, a1.w};
            const float b[4] = {b0.x, b0.y, b0.z, b0.w};
#pragma unroll
            for (int i = 0; i < 8; i++)
#pragma unroll
                for (int j = 0; j < 4; j++) acc[i][j] += a[i] * b[j];
        }
        __syncthreads();
    }

    float bv[4];
#pragma unroll
    for (int j = 0; j < 4; j++) bv[j] = bias ? bias[bn + tx * 4 + j] : 0.f;
#pragma unroll
    for (int i = 0; i < 8; i++) {
        const int gm = bm + ty * 8 + i;
        if (gm >= M) continue;
        float* cp = C + (size_t)gm * ldc + bn + tx * 4;
        float4 r0 = make_float4(acc[i][0] + bv[0], acc[i][1] + bv[1],
                                acc[i][2] + bv[2], acc[i][3] + bv[3]);
        *(float4*)cp = r0;
    }
}

// ---------------- decoder input: [sos; emb[y]] ----------------
__global__ void decin_k(const int* __restrict__ y, const float* __restrict__ emb,
                        float* __restrict__ dst)
{
    const int i = blockIdx.x * blockDim.x + threadIdx.x;
    if (i >= U1 * BB * EE) return;
    const int e = i % EE;
    const int b = (i / EE) % BB;
    const int u = i / (EE * BB);
    float v = 0.f;
    if (u > 0) {
        const int tok = y[(u - 1) * BB + b];
        v = emb[(size_t)tok * EE + e];
    }
    dst[i] = v;
}

// ---------------- persistent LSTM recurrence (register-tiled) ----------------
// 128 blocks x 256 threads. Block bid owns 32 gate-rows (4 gates x 8 units).
// Warp w owns local rows c=w*4..w*4+3, all 8 batches; lanes split K with a
// 16B-interleaved swizzle: lane l, iter kk covers k = kk*128 + l*4 + [0..3].
// Inner loop: 12 LDS.128 feed 64 fma.rn.f32x2 per 4-k slab.
__global__ __launch_bounds__(256) void lstm_rec(
    const float* __restrict__ Whh, const float* __restrict__ xp,
    float* __restrict__ hout, int nsteps)
{
    extern __shared__ float sm[];
    float* Ws = sm;                       // 32 * WSTR
    float* Hs = Ws + 32 * WSTR;           // 8 * WSTR
    float* Rs = Hs + 8 * WSTR;            // 256 * 36 (lane-reduction transpose)
    float* Gt = Rs + 256 * 36;            // 256 gates
    float* Cs = Gt + 256;                 // 64 cell states

    const int tid  = threadIdx.x;
    const int bid  = blockIdx.x;
    const int hbase = bid * 8;
    const int w    = tid >> 5;
    const int lane = tid & 31;

    // Load weight slice: Ws[c][k], c = gate*8 + unit
    for (int c = 0; c < 32; c++) {
        const int q = c >> 3, r = c & 7;
        const float4* src = (const float4*)(Whh + ((size_t)q * HH + hbase + r) * HH);
        ((float4*)(Ws + c * WSTR))[tid] = src[tid];
    }
    if (tid < 64) {
        Cs[tid] = 0.f;
        const int r = tid >> 3, b = tid & 7;
        g_h[0][b * HH + hbase + r] = 0.f;
        __threadfence();
    }

    volatile unsigned* vgen = &g_bargen;
    const unsigned base = *vgen;
    grid_bar(base + 1, NBLK);
    unsigned bt = base + 2;

    // output role: thread tid owns output o=tid -> (cc_o, b_o)
    const int cc_o = (tid >> 5) * 4 + ((tid & 31) >> 3);
    const int b_o  = tid & 7;
    const int q_o  = cc_o >> 3, r_o = cc_o & 7;

    // compute role pointers (warp w rows)
    const ulonglong2* wp0 = (const ulonglong2*)(Ws + (w * 4 + 0) * WSTR);
    const ulonglong2* wp1 = (const ulonglong2*)(Ws + (w * 4 + 1) * WSTR);
    const ulonglong2* wp2 = (const ulonglong2*)(Ws + (w * 4 + 2) * WSTR);
    const ulonglong2* wp3 = (const ulonglong2*)(Ws + (w * 4 + 3) * WSTR);

    for (int t = 0; t < nsteps; t++) {
        const int rp  = t & 1;
        const int wpb = (t + 1) & 1;
        const float4* hbuf = (const float4*)g_h[rp];
#pragma unroll
        for (int i = 0; i < 8; i++) {
            const int idx = tid + i * 256;           // 0..2047 float4s
            ((float4*)(Hs + (idx >> 8) * WSTR))[idx & 255] = hbuf[idx];
        }
        const float xg = xp[((size_t)t * BB + b_o) * G4 + q_o * HH + hbase + r_o];
        __syncthreads();

        unsigned long long acc[4][8];
#pragma unroll
        for (int c = 0; c < 4; c++)
#pragma unroll
            for (int b = 0; b < 8; b++) acc[c][b] = 0ull;

#pragma unroll
        for (int kk = 0; kk < 8; kk++) {
            const int o = kk * 32 + lane;
            const ulonglong2 wv0 = wp0[o];
            const ulonglong2 wv1 = wp1[o];
            const ulonglong2 wv2 = wp2[o];
            const ulonglong2 wv3 = wp3[o];
#pragma unroll
            for (int b = 0; b < 8; b++) {
                const ulonglong2 hv = ((const ulonglong2*)(Hs + b * WSTR))[o];
                ffma2(acc[0][b], wv0.x, hv.x); ffma2(acc[0][b], wv0.y, hv.y);
                ffma2(acc[1][b], wv1.x, hv.x); ffma2(acc[1][b], wv1.y, hv.y);
                ffma2(acc[2][b], wv2.x, hv.x); ffma2(acc[2][b], wv2.y, hv.y);
                ffma2(acc[3][b], wv3.x, hv.x); ffma2(acc[3][b], wv3.y, hv.y);
            }
        }

        // lane-partials -> SMEM transpose (conflict-free both ways)
#pragma unroll
        for (int c = 0; c < 4; c++)
#pragma unroll
            for (int b = 0; b < 8; b++)
                Rs[(w * 32 + c * 8 + b) * 36 + lane] = hsum2(acc[c][b]);
        __syncthreads();

        // thread tid reduces its output's 32 lane-partials
        {
            const float4* rp4 = (const float4*)(Rs + tid * 36);
            float4 s4 = rp4[0];
#pragma unroll
            for (int j = 1; j < 8; j++) {
                const float4 v = rp4[j];
                s4.x += v.x; s4.y += v.y; s4.z += v.z; s4.w += v.w;
            }
            Gt[cc_o * 8 + b_o] = (s4.x + s4.y) + (s4.z + s4.w) + xg;
        }
        __syncthreads();

        if (tid < 64) {
            const int r2 = tid >> 3, b2 = tid & 7;
            const float gi = Gt[(0  + r2) * 8 + b2];
            const float gf = Gt[(8  + r2) * 8 + b2];
            const float gc = Gt[(16 + r2) * 8 + b2];
            const float go = Gt[(24 + r2) * 8 + b2];
            const float si = 1.f / (1.f + expf(-gi));
            const float sf = 1.f / (1.f + expf(-gf));
            const float so = 1.f / (1.f + expf(-go));
            const float tg = tanhf(gc);
            const float cn = sf * Cs[tid] + si * tg;
            Cs[tid] = cn;
            const float hv = so * tanhf(cn);
            g_h[wpb][b2 * HH + hbase + r2] = hv;
            hout[((size_t)t * BB + b2) * HH + hbase + r2] = hv;
            __threadfence();
        }
        grid_bar(bt, NBLK);
        bt++;
    }
}

// ---------------- final broadcast add ----------------
__global__ __launch_bounds__(256) void addk(
    const float* __restrict__ lf, const float* __restrict__ lg,
    const float* __restrict__ bias, float* __restrict__ out)
{
    const int u = blockIdx.x, t = blockIdx.y, b = blockIdx.z;
    const int v4 = threadIdx.x;
    const float4 a = ((const float4*)(lf + ((size_t)(t * BB + b)) * VV))[v4];
    const float4 c = ((const float4*)(lg + ((size_t)(u * BB + b)) * VV))[v4];
    const float4 bb = ((const float4*)bias)[v4];
    float4 r;
    r.x = a.x + c.x + bb.x; r.y = a.y + c.y + bb.y;
    r.z = a.z + c.z + bb.z; r.w = a.w + c.w + bb.w;
    ((float4*)(out + (((size_t)b * TT + t) * U1 + u) * VV))[v4] = r;
}

// ---------------- launch ----------------
extern "C" void kernel_launch(void* const* d_in, const int* in_sizes, int n_in,
                              void* d_out, int out_size)
{
    const float* x        = (const float*)d_in[0];
    const int*   y        = (const int*)  d_in[2];
    const float* enc_Wih  = (const float*)d_in[4];
    const float* enc_Whh  = (const float*)d_in[5];
    const float* enc_b    = (const float*)d_in[6];
    const float* emb      = (const float*)d_in[7];
    const float* dec_Wih  = (const float*)d_in[8];
    const float* dec_Whh  = (const float*)d_in[9];
    const float* dec_b    = (const float*)d_in[10];
    const float* fc_W     = (const float*)d_in[11];
    const float* fc_b     = (const float*)d_in[12];
    float* out = (float*)d_out;

    float *xp_enc, *xp_dec, *decin, *f, *g, *lf, *lg;
    cudaGetSymbolAddress((void**)&xp_enc, g_xp_enc);
    cudaGetSymbolAddress((void**)&xp_dec, g_xp_dec);
    cudaGetSymbolAddress((void**)&decin,  g_decin);
    cudaGetSymbolAddress((void**)&f,      g_f);
    cudaGetSymbolAddress((void**)&g,      g_gg);
    cudaGetSymbolAddress((void**)&lf,     g_lf);
    cudaGetSymbolAddress((void**)&lg,     g_lg);

    const int smem = (32 * WSTR + 8 * WSTR + 256 * 36 + 256 + 64) * (int)sizeof(float);
    cudaFuncSetAttribute(lstm_rec, cudaFuncAttributeMaxDynamicSharedMemorySize, smem);

    // 1) Encoder input projection: xp_enc[1024,4096] = x @ enc_Wih^T + b
    gemm_tn<<<dim3(G4 / 64, (TT * BB) / 128), 256>>>(
        x, enc_Wih, enc_b, xp_enc, TT * BB, G4, II, II, II, G4);

    // 2) Decoder input sequence + projection
    decin_k<<<(U1 * BB * EE + 255) / 256, 256>>>(y, emb, decin);
    gemm_tn<<<dim3(G4 / 64, (U1 * BB + 127) / 128), 256>>>(
        decin, dec_Wih, dec_b, xp_dec, U1 * BB, G4, EE, EE, EE, G4);

    // 3) Recurrences (persistent, grid-barrier)
    lstm_rec<<<NBLK, 256, smem>>>(enc_Whh, xp_enc, f, TT);
    lstm_rec<<<NBLK, 256, smem>>>(dec_Whh, xp_dec, g, U1);

    // 4) Joint projections (fc_W is [V][2048])
    gemm_tn<<<dim3(VV / 64, (TT * BB) / 128), 256>>>(
        f, fc_W, (const float*)0, lf, TT * BB, VV, HH, HH, HH + HH, VV);
    gemm_tn<<<dim3(VV / 64, (U1 * BB + 127) / 128), 256>>>(
        g, fc_W + HH, (const float*)0, lg, U1 * BB, VV, HH, HH, HH + HH, VV);

    // 5) Broadcast add -> out [B][T][U+1][V]
    addk<<<dim3(U1, TT, BB), 256>>>(lf, lg, fc_b, out);
}